// round 3
// baseline (speedup 1.0000x reference)
#include <cuda_runtime.h>

#define SEQL 20
#define EMB  20
#define NMAX 671744
#define EMAX 4000000
#define NBATCH 8192
#define HID  300
#define NC   22
#define LAT  1640   // 82*20

// ---------------- scratch (static device globals; no runtime alloc) -------
__device__ int   g_deg[NMAX];
__device__ int   g_rowstart[NMAX];
__device__ int   g_cursor[NMAX];
__device__ float g_dinv[NMAX];
__device__ float g_hs[(size_t)NMAX * EMB];    // features ping
__device__ float g_agg[(size_t)NMAX * EMB];   // features pong
__device__ int   g_src[EMAX];
__device__ int   g_dst[EMAX];
__device__ int   g_csr[EMAX];
__device__ float g_fc1[(size_t)NBATCH * HID];
__device__ int   g_is64;
__device__ int   g_total;

// ---------------- helpers -------------------------------------------------
__device__ __forceinline__ unsigned long long fma2(unsigned long long a,
                                                   unsigned long long b,
                                                   unsigned long long c) {
    unsigned long long d;
    asm("fma.rn.f32x2 %0, %1, %2, %3;" : "=l"(d) : "l"(a), "l"(b), "l"(c));
    return d;
}
__device__ __forceinline__ float2 unpack2(unsigned long long v) {
    float x, y;
    asm("mov.b64 {%0, %1}, %2;" : "=f"(x), "=f"(y) : "l"(v));
    return make_float2(x, y);
}

// ---------------- graph prep ---------------------------------------------
__global__ void k_detect(const int* __restrict__ ei32) {
    if (blockIdx.x == 0 && threadIdx.x == 0) {
        int all0 = 1;
        for (int q = 1; q < 257; q += 2)
            if (ei32[q] != 0) { all0 = 0; break; }
        g_is64 = all0;   // int64 little-endian: high words of small values are 0
    }
}

__global__ void k_deg_init(int n) {
    int i = blockIdx.x * blockDim.x + threadIdx.x;
    if (i < n) g_deg[i] = 0;
    if (i == 0) g_total = 0;
}

__global__ void k_edges_prep(const void* __restrict__ eiv, int E) {
    int e = blockIdx.x * blockDim.x + threadIdx.x;
    if (e >= E) return;
    int s, d;
    if (g_is64) {
        const long long* p = (const long long*)eiv;
        s = (int)p[e];
        d = (int)p[(size_t)E + e];
    } else {
        const int* p = (const int*)eiv;
        s = p[e];
        d = p[E + e];
    }
    g_src[e] = s;
    g_dst[e] = d;
    atomicAdd(&g_deg[d], 1);
}

// segment assignment (order-free prefix allocation) + dinv
__global__ void k_offsets(int n) {
    int i = blockIdx.x * blockDim.x + threadIdx.x;
    if (i >= n) return;
    int d = g_deg[i];
    g_dinv[i] = rsqrtf((float)(d + 1));     // +1 self loop
    int r = atomicAdd(&g_total, d);
    g_rowstart[i] = r;
    g_cursor[i] = r;
}

__global__ void k_place(int E) {
    int e = blockIdx.x * blockDim.x + threadIdx.x;
    if (e >= E) return;
    int d = g_dst[e];
    int pos = atomicAdd(&g_cursor[d], 1);
    g_csr[pos] = g_src[e];
}

// ---------------- layer 1: hs = (x @ W1) * dinv ---------------------------
__global__ __launch_bounds__(256) void k_layer1(const float* __restrict__ x,
                                                const float* __restrict__ W,
                                                int n) {
    __shared__ __align__(16) float sW[SEQL * EMB];
    for (int t = threadIdx.x; t < SEQL * EMB; t += 256) sW[t] = W[t];
    __syncthreads();
    int i = blockIdx.x * 256 + threadIdx.x;
    if (i >= n) return;
    float dinv = g_dinv[i];
    float xi[SEQL];
    const float4* xp = (const float4*)(x + (size_t)i * SEQL);
#pragma unroll
    for (int q = 0; q < SEQL / 4; q++) {
        float4 v = __ldg(xp + q);
        xi[4*q] = v.x; xi[4*q+1] = v.y; xi[4*q+2] = v.z; xi[4*q+3] = v.w;
    }
    float o[EMB];
#pragma unroll
    for (int j = 0; j < EMB; j++) o[j] = 0.f;
#pragma unroll
    for (int k = 0; k < SEQL; k++) {
        float xk = xi[k];
#pragma unroll
        for (int q = 0; q < EMB / 4; q++) {
            float4 w = *(const float4*)&sW[k * EMB + 4 * q];
            o[4*q]   = fmaf(xk, w.x, o[4*q]);
            o[4*q+1] = fmaf(xk, w.y, o[4*q+1]);
            o[4*q+2] = fmaf(xk, w.z, o[4*q+2]);
            o[4*q+3] = fmaf(xk, w.w, o[4*q+3]);
        }
    }
    float4* hp = (float4*)(g_hs + (size_t)i * EMB);
#pragma unroll
    for (int q = 0; q < EMB / 4; q++)
        hp[q] = make_float4(o[4*q]*dinv, o[4*q+1]*dinv, o[4*q+2]*dinv, o[4*q+3]*dinv);
}

// ---- fused gather + layer2:  hout = relu((self+Σ hin[src])*dinv + b1) @ W2 * dinv
// DIR=0: hin=g_hs, hout=g_agg.  (templated to avoid host symbol lookups)
template <int DIR>
__global__ __launch_bounds__(256) void k_gather_layer2(const float* __restrict__ b1,
                                                       const float* __restrict__ W,
                                                       int n) {
    const float* hin  = DIR ? g_agg : g_hs;
    float*       hout = DIR ? g_hs  : g_agg;
    __shared__ __align__(16) float sW[EMB * EMB];
    __shared__ float sb[EMB];
    for (int t = threadIdx.x; t < EMB * EMB; t += 256) sW[t] = W[t];
    if (threadIdx.x < EMB) sb[threadIdx.x] = b1[threadIdx.x];
    __syncthreads();
    int i = blockIdx.x * 256 + threadIdx.x;
    if (i >= n) return;
    float acc[EMB];
    const float4* self = (const float4*)(hin + (size_t)i * EMB);
#pragma unroll
    for (int q = 0; q < EMB / 4; q++) {
        float4 v = self[q];
        acc[4*q] = v.x; acc[4*q+1] = v.y; acc[4*q+2] = v.z; acc[4*q+3] = v.w;
    }
    int r0 = g_rowstart[i];
    int r1 = r0 + g_deg[i];
    for (int r = r0; r < r1; r++) {
        int s = __ldg(&g_csr[r]);
        const float4* sp = (const float4*)(hin + (size_t)s * EMB);
#pragma unroll
        for (int q = 0; q < EMB / 4; q++) {
            float4 v = __ldg(sp + q);
            acc[4*q]   += v.x;
            acc[4*q+1] += v.y;
            acc[4*q+2] += v.z;
            acc[4*q+3] += v.w;
        }
    }
    float dinv = g_dinv[i];
#pragma unroll
    for (int k = 0; k < EMB; k++)
        acc[k] = fmaxf(fmaf(acc[k], dinv, sb[k]), 0.f);
    float o[EMB];
#pragma unroll
    for (int j = 0; j < EMB; j++) o[j] = 0.f;
#pragma unroll
    for (int k = 0; k < EMB; k++) {
        float tk = acc[k];
#pragma unroll
        for (int q = 0; q < EMB / 4; q++) {
            float4 w = *(const float4*)&sW[k * EMB + 4 * q];
            o[4*q]   = fmaf(tk, w.x, o[4*q]);
            o[4*q+1] = fmaf(tk, w.y, o[4*q+1]);
            o[4*q+2] = fmaf(tk, w.z, o[4*q+2]);
            o[4*q+3] = fmaf(tk, w.w, o[4*q+3]);
        }
    }
    float4* hp = (float4*)(hout + (size_t)i * EMB);
#pragma unroll
    for (int q = 0; q < EMB / 4; q++)
        hp[q] = make_float4(o[4*q]*dinv, o[4*q+1]*dinv, o[4*q+2]*dinv, o[4*q+3]*dinv);
}

// ---- fused gather + final relu: g_hs = relu((self+Σ g_agg[src])*dinv + b2)
__global__ __launch_bounds__(256) void k_gather_final(const float* __restrict__ b2,
                                                      int n) {
    const float* hin  = g_agg;
    float*       hout = g_hs;
    __shared__ float sb[EMB];
    if (threadIdx.x < EMB) sb[threadIdx.x] = b2[threadIdx.x];
    __syncthreads();
    int i = blockIdx.x * 256 + threadIdx.x;
    if (i >= n) return;
    float acc[EMB];
    const float4* self = (const float4*)(hin + (size_t)i * EMB);
#pragma unroll
    for (int q = 0; q < EMB / 4; q++) {
        float4 v = self[q];
        acc[4*q] = v.x; acc[4*q+1] = v.y; acc[4*q+2] = v.z; acc[4*q+3] = v.w;
    }
    int r0 = g_rowstart[i];
    int r1 = r0 + g_deg[i];
    for (int r = r0; r < r1; r++) {
        int s = __ldg(&g_csr[r]);
        const float4* sp = (const float4*)(hin + (size_t)s * EMB);
#pragma unroll
        for (int q = 0; q < EMB / 4; q++) {
            float4 v = __ldg(sp + q);
            acc[4*q]   += v.x;
            acc[4*q+1] += v.y;
            acc[4*q+2] += v.z;
            acc[4*q+3] += v.w;
        }
    }
    float dinv = g_dinv[i];
    float4* hp = (float4*)(hout + (size_t)i * EMB);
#pragma unroll
    for (int q = 0; q < EMB / 4; q++) {
        float4 v = make_float4(fmaxf(fmaf(acc[4*q],   dinv, sb[4*q]),   0.f),
                               fmaxf(fmaf(acc[4*q+1], dinv, sb[4*q+1]), 0.f),
                               fmaxf(fmaf(acc[4*q+2], dinv, sb[4*q+2]), 0.f),
                               fmaxf(fmaf(acc[4*q+3], dinv, sb[4*q+3]), 0.f));
        hp[q] = v;
    }
}

// ---------------- fc1 GEMM: relu(latent[8192,1640] @ Wf[1640,300] + bf) ---
// latent lives in g_hs. BM=128 BN=64 BK=8, 256 thr, TM=8 TN=4; pair-packed A
// + duplicated B in smem so the hot loop is pure LDS.128 + fma.f32x2.
#define BM 128
#define BN 64
#define BK 8
__global__ __launch_bounds__(256) void k_fc1(const float* __restrict__ Wf,
                                             const float* __restrict__ bf) {
    __shared__ __align__(16) float As[BK][BM + 4];
    __shared__ __align__(16) float Bsd[BK][2 * BN + 4];
    const int tid  = threadIdx.x;
    const int row0 = blockIdx.x * BM;
    const int col0 = blockIdx.y * BN;
    const int tm = (tid >> 4) * 8;      // 0..120
    const int tn = (tid & 15) * 4;      // 0..60
    const int arow = tid >> 1;          // 0..127
    const int ak   = (tid & 1) * 4;     // 0 or 4
    const int brow = tid >> 4;          // 0..7 (tid<128)
    const int bc   = (tid & 15) * 4;    // 0..60

    unsigned long long acc[4][4];       // [m-pair][col]
#pragma unroll
    for (int p = 0; p < 4; p++)
#pragma unroll
        for (int q = 0; q < 4; q++) acc[p][q] = 0ULL;

    for (int k0 = 0; k0 < LAT; k0 += BK) {
        float4 va = *(const float4*)(g_hs + (size_t)(row0 + arow) * LAT + (k0 + ak));
        As[ak + 0][arow] = va.x;
        As[ak + 1][arow] = va.y;
        As[ak + 2][arow] = va.z;
        As[ak + 3][arow] = va.w;
        if (tid < 128) {
            int gc = col0 + bc;
            float4 vb = make_float4(0.f, 0.f, 0.f, 0.f);
            if (gc < HID)
                vb = *(const float4*)(Wf + (size_t)(k0 + brow) * HID + gc);
            // duplicated pairs {x,x,y,y,z,z,w,w}
            *(float4*)&Bsd[brow][2 * bc]     = make_float4(vb.x, vb.x, vb.y, vb.y);
            *(float4*)&Bsd[brow][2 * bc + 4] = make_float4(vb.z, vb.z, vb.w, vb.w);
        }
        __syncthreads();
#pragma unroll
        for (int k = 0; k < BK; k++) {
            ulonglong2 a01 = *(const ulonglong2*)&As[k][tm];       // pairs (m,m+1)(m+2,m+3)
            ulonglong2 a23 = *(const ulonglong2*)&As[k][tm + 4];
            ulonglong2 b01 = *(const ulonglong2*)&Bsd[k][2 * tn];      // dup cols tn, tn+1
            ulonglong2 b23 = *(const ulonglong2*)&Bsd[k][2 * tn + 4];  // dup cols tn+2, tn+3
            acc[0][0] = fma2(a01.x, b01.x, acc[0][0]);
            acc[0][1] = fma2(a01.x, b01.y, acc[0][1]);
            acc[0][2] = fma2(a01.x, b23.x, acc[0][2]);
            acc[0][3] = fma2(a01.x, b23.y, acc[0][3]);
            acc[1][0] = fma2(a01.y, b01.x, acc[1][0]);
            acc[1][1] = fma2(a01.y, b01.y, acc[1][1]);
            acc[1][2] = fma2(a01.y, b23.x, acc[1][2]);
            acc[1][3] = fma2(a01.y, b23.y, acc[1][3]);
            acc[2][0] = fma2(a23.x, b01.x, acc[2][0]);
            acc[2][1] = fma2(a23.x, b01.y, acc[2][1]);
            acc[2][2] = fma2(a23.x, b23.x, acc[2][2]);
            acc[2][3] = fma2(a23.x, b23.y, acc[2][3]);
            acc[3][0] = fma2(a23.y, b01.x, acc[3][0]);
            acc[3][1] = fma2(a23.y, b01.y, acc[3][1]);
            acc[3][2] = fma2(a23.y, b23.x, acc[3][2]);
            acc[3][3] = fma2(a23.y, b23.y, acc[3][3]);
        }
        __syncthreads();
    }
    int gc = col0 + tn;
    if (gc < HID) {   // HID%4==0 so the whole float4 is valid
        float bb[4];
#pragma unroll
        for (int q = 0; q < 4; q++) bb[q] = bf[gc + q];
#pragma unroll
        for (int p = 0; p < 4; p++) {
            float2 u0 = unpack2(acc[p][0]);
            float2 u1 = unpack2(acc[p][1]);
            float2 u2 = unpack2(acc[p][2]);
            float2 u3 = unpack2(acc[p][3]);
            int r = row0 + tm + 2 * p;
            float4 vlo = make_float4(fmaxf(u0.x + bb[0], 0.f), fmaxf(u1.x + bb[1], 0.f),
                                     fmaxf(u2.x + bb[2], 0.f), fmaxf(u3.x + bb[3], 0.f));
            float4 vhi = make_float4(fmaxf(u0.y + bb[0], 0.f), fmaxf(u1.y + bb[1], 0.f),
                                     fmaxf(u2.y + bb[2], 0.f), fmaxf(u3.y + bb[3], 0.f));
            *(float4*)(g_fc1 + (size_t)r * HID + gc)       = vlo;
            *(float4*)(g_fc1 + (size_t)(r + 1) * HID + gc) = vhi;
        }
    }
}

// ---------------- out: [8192,300] @ [300,22] + out_b ----------------------
__global__ __launch_bounds__(256) void k_out(const float* __restrict__ Wo,
                                             const float* __restrict__ bo,
                                             float* __restrict__ out) {
    __shared__ float sW[HID * NC];
    __shared__ float sb[NC];
    for (int t = threadIdx.x; t < HID * NC; t += 256) sW[t] = Wo[t];
    if (threadIdx.x < NC) sb[threadIdx.x] = bo[threadIdx.x];
    __syncthreads();
    int w = threadIdx.x >> 5, lane = threadIdx.x & 31;
    int rbase = blockIdx.x * 64 + w * 8;
#pragma unroll 1
    for (int r8 = 0; r8 < 8; r8++) {
        int r = rbase + r8;
        const float4* fr4 = (const float4*)(g_fc1 + (size_t)r * HID);
        if (lane < NC) {
            float accv = 0.f;
#pragma unroll 5
            for (int k4 = 0; k4 < HID / 4; k4++) {
                float4 v = fr4[k4];
                int k = 4 * k4;
                accv = fmaf(v.x, sW[(k + 0) * NC + lane], accv);
                accv = fmaf(v.y, sW[(k + 1) * NC + lane], accv);
                accv = fmaf(v.z, sW[(k + 2) * NC + lane], accv);
                accv = fmaf(v.w, sW[(k + 3) * NC + lane], accv);
            }
            out[(size_t)r * NC + lane] = accv + sb[lane];
        }
    }
}

// ---------------- launch --------------------------------------------------
extern "C" void kernel_launch(void* const* d_in, const int* in_sizes, int n_in,
                              void* d_out, int out_size) {
    const float* x    = (const float*)d_in[0];
    const void*  ei   = d_in[1];
    const float* W1   = (const float*)d_in[3];
    const float* b1   = (const float*)d_in[4];
    const float* W2   = (const float*)d_in[5];
    const float* b2   = (const float*)d_in[6];
    const float* fc1W = (const float*)d_in[7];
    const float* fc1b = (const float*)d_in[8];
    const float* outW = (const float*)d_in[9];
    const float* outb = (const float*)d_in[10];
    float* out = (float*)d_out;

    int N = in_sizes[0] / SEQL;
    int E = in_sizes[1] / 2;
    int nb = (N + 255) / 256;
    int eb = (E + 255) / 256;

    k_detect<<<1, 32>>>((const int*)ei);
    k_deg_init<<<nb, 256>>>(N);
    k_edges_prep<<<eb, 256>>>(ei, E);
    k_offsets<<<nb, 256>>>(N);
    k_place<<<eb, 256>>>(E);
    k_layer1<<<nb, 256>>>(x, W1, N);                 // -> g_hs
    k_gather_layer2<0><<<nb, 256>>>(b1, W2, N);      // g_hs -> g_agg
    k_gather_final<<<nb, 256>>>(b2, N);              // g_agg -> g_hs (latent)
    dim3 gfc(NBATCH / BM, (HID + BN - 1) / BN);
    k_fc1<<<gfc, 256>>>(fc1W, fc1b);
    k_out<<<NBATCH / 64, 256>>>(outW, outb, out);
}

// round 4
// speedup vs baseline: 1.0239x; 1.0239x over previous
#include <cuda_runtime.h>

#define SEQL 20
#define EMB  20
#define NMAX 671744
#define EMAX 4000000
#define NBATCH 8192
#define HID  300
#define NC   22
#define LAT  1640   // 82*20

// ---------------- scratch (static device globals; no runtime alloc) -------
__device__ int   g_deg[NMAX];
__device__ int   g_rowstart[NMAX];
__device__ int   g_cursor[NMAX];
__device__ float g_dinv[NMAX];
__device__ __align__(16) float g_hs[(size_t)NMAX * EMB];   // raw h = in@W
__device__ __align__(16) float g_agg[(size_t)NMAX * EMB];  // gathered/activated
__device__ int   g_src[EMAX];
__device__ int   g_dst[EMAX];
__device__ int   g_csr[EMAX];
__device__ __align__(16) float g_fc1[(size_t)NBATCH * HID];
__device__ int   g_is64;
__device__ int   g_total;

// ---------------- helpers -------------------------------------------------
__device__ __forceinline__ unsigned long long fma2(unsigned long long a,
                                                   unsigned long long b,
                                                   unsigned long long c) {
    unsigned long long d;
    asm("fma.rn.f32x2 %0, %1, %2, %3;" : "=l"(d) : "l"(a), "l"(b), "l"(c));
    return d;
}
__device__ __forceinline__ float2 unpack2(unsigned long long v) {
    float x, y;
    asm("mov.b64 {%0, %1}, %2;" : "=f"(x), "=f"(y) : "l"(v));
    return make_float2(x, y);
}

// ---------------- graph prep ---------------------------------------------
__global__ void k_detect(const int* __restrict__ ei32) {
    if (blockIdx.x == 0 && threadIdx.x == 0) {
        int all0 = 1;
        for (int q = 1; q < 257; q += 2)
            if (ei32[q] != 0) { all0 = 0; break; }
        g_is64 = all0;   // int64 little-endian: high words of small values are 0
    }
}

__global__ void k_deg_init(int n) {
    int i = blockIdx.x * blockDim.x + threadIdx.x;
    if (i < n) g_deg[i] = 0;
    if (i == 0) g_total = 0;
}

__global__ void k_edges_prep(const void* __restrict__ eiv, int E) {
    int e = blockIdx.x * blockDim.x + threadIdx.x;
    if (e >= E) return;
    int s, d;
    if (g_is64) {
        const long long* p = (const long long*)eiv;
        s = (int)p[e];
        d = (int)p[(size_t)E + e];
    } else {
        const int* p = (const int*)eiv;
        s = p[e];
        d = p[E + e];
    }
    g_src[e] = s;
    g_dst[e] = d;
    atomicAdd(&g_deg[d], 1);
}

// segment offsets: block-wide scan + one atomic per block
__global__ __launch_bounds__(256) void k_offsets(int n) {
    __shared__ int sdata[256];
    __shared__ int sbase;
    int tx = threadIdx.x;
    int i = blockIdx.x * 256 + tx;
    int d = (i < n) ? g_deg[i] : 0;
    sdata[tx] = d;
    __syncthreads();
#pragma unroll
    for (int off = 1; off < 256; off <<= 1) {
        int y = (tx >= off) ? sdata[tx - off] : 0;
        __syncthreads();
        sdata[tx] += y;
        __syncthreads();
    }
    if (tx == 255) sbase = atomicAdd(&g_total, sdata[255]);
    __syncthreads();
    if (i < n) {
        int r = sbase + sdata[tx] - d;   // exclusive prefix
        g_dinv[i] = rsqrtf((float)(d + 1));   // +1 self loop
        g_rowstart[i] = r;
        g_cursor[i] = r;
    }
}

__global__ void k_place(int E) {
    int e = blockIdx.x * blockDim.x + threadIdx.x;
    if (e >= E) return;
    int d = g_dst[e];
    int pos = atomicAdd(&g_cursor[d], 1);
    g_csr[pos] = g_src[e];
}

// ---------------- node-parallel 20x20 GEMM: g_hs = in @ W (raw) -----------
// SRC=0: in = external pointer (x). SRC=1: in = g_agg.
template <int SRC>
__global__ __launch_bounds__(256) void k_mm20(const float* __restrict__ xin,
                                              const float* __restrict__ W,
                                              int n) {
    const float* in = SRC ? (const float*)g_agg : xin;
    __shared__ __align__(16) float sW[EMB * EMB];
    for (int t = threadIdx.x; t < EMB * EMB; t += 256) sW[t] = W[t];
    __syncthreads();
    int i = blockIdx.x * 256 + threadIdx.x;
    if (i >= n) return;
    float xi[EMB];
    const float4* xp = (const float4*)(in + (size_t)i * EMB);
#pragma unroll
    for (int q = 0; q < EMB / 4; q++) {
        float4 v = __ldg(xp + q);
        xi[4*q] = v.x; xi[4*q+1] = v.y; xi[4*q+2] = v.z; xi[4*q+3] = v.w;
    }
    float o[EMB];
#pragma unroll
    for (int j = 0; j < EMB; j++) o[j] = 0.f;
#pragma unroll
    for (int k = 0; k < EMB; k++) {
        float xk = xi[k];
#pragma unroll
        for (int q = 0; q < EMB / 4; q++) {
            float4 w = *(const float4*)&sW[k * EMB + 4 * q];
            o[4*q]   = fmaf(xk, w.x, o[4*q]);
            o[4*q+1] = fmaf(xk, w.y, o[4*q+1]);
            o[4*q+2] = fmaf(xk, w.z, o[4*q+2]);
            o[4*q+3] = fmaf(xk, w.w, o[4*q+3]);
        }
    }
    float4* hp = (float4*)(g_hs + (size_t)i * EMB);
#pragma unroll
    for (int q = 0; q < EMB / 4; q++)
        hp[q] = make_float4(o[4*q], o[4*q+1], o[4*q+2], o[4*q+3]);
}

// ---- coalesced gather: g_agg = relu(dinv_i*(dinv_i*h_i + Σ dinv_s*h_s) + b)
// 5 threads per node (one float4 chunk each); lanes of a row are consecutive.
#define GT 320   // threads per block = 64 nodes
__global__ __launch_bounds__(GT) void k_gather(const float* __restrict__ bias,
                                               int n) {
    __shared__ float sb[EMB];
    if (threadIdx.x < EMB) sb[threadIdx.x] = bias[threadIdx.x];
    __syncthreads();
    int t = blockIdx.x * GT + threadIdx.x;
    int i = t / 5, q = t % 5;
    if (i >= n) return;
    float di = g_dinv[i];
    const float4* hq = (const float4*)g_hs;   // row i chunk q at i*5+q
    float4 v = __ldg(hq + (size_t)i * 5 + q);
    float4 acc;
    acc.x = v.x * di; acc.y = v.y * di; acc.z = v.z * di; acc.w = v.w * di;
    int r = g_rowstart[i];
    int rend = r + g_deg[i];
    for (; r + 2 <= rend; r += 2) {
        int s0 = __ldg(&g_csr[r]);
        int s1 = __ldg(&g_csr[r + 1]);
        float ds0 = __ldg(&g_dinv[s0]);
        float ds1 = __ldg(&g_dinv[s1]);
        float4 v0 = __ldg(hq + (size_t)s0 * 5 + q);
        float4 v1 = __ldg(hq + (size_t)s1 * 5 + q);
        acc.x = fmaf(v0.x, ds0, acc.x);
        acc.y = fmaf(v0.y, ds0, acc.y);
        acc.z = fmaf(v0.z, ds0, acc.z);
        acc.w = fmaf(v0.w, ds0, acc.w);
        acc.x = fmaf(v1.x, ds1, acc.x);
        acc.y = fmaf(v1.y, ds1, acc.y);
        acc.z = fmaf(v1.z, ds1, acc.z);
        acc.w = fmaf(v1.w, ds1, acc.w);
    }
    if (r < rend) {
        int s0 = __ldg(&g_csr[r]);
        float ds0 = __ldg(&g_dinv[s0]);
        float4 v0 = __ldg(hq + (size_t)s0 * 5 + q);
        acc.x = fmaf(v0.x, ds0, acc.x);
        acc.y = fmaf(v0.y, ds0, acc.y);
        acc.z = fmaf(v0.z, ds0, acc.z);
        acc.w = fmaf(v0.w, ds0, acc.w);
    }
    float4 o;
    o.x = fmaxf(fmaf(acc.x, di, sb[4*q + 0]), 0.f);
    o.y = fmaxf(fmaf(acc.y, di, sb[4*q + 1]), 0.f);
    o.z = fmaxf(fmaf(acc.z, di, sb[4*q + 2]), 0.f);
    o.w = fmaxf(fmaf(acc.w, di, sb[4*q + 3]), 0.f);
    ((float4*)g_agg)[(size_t)i * 5 + q] = o;
}

// ---------------- fc1 GEMM: relu(latent[8192,1640] @ Wf[1640,300] + bf) ---
// latent lives in g_agg. BM=128 BN=64 BK=8, 256 thr, TM=8 TN=4; pair-packed A
// + duplicated B in smem so the hot loop is pure LDS.128 + fma.f32x2.
#define BM 128
#define BN 64
#define BK 8
__global__ __launch_bounds__(256) void k_fc1(const float* __restrict__ Wf,
                                             const float* __restrict__ bf) {
    __shared__ __align__(16) float As[BK][BM + 4];
    __shared__ __align__(16) float Bsd[BK][2 * BN + 4];
    const int tid  = threadIdx.x;
    const int row0 = blockIdx.x * BM;
    const int col0 = blockIdx.y * BN;
    const int tm = (tid >> 4) * 8;      // 0..120
    const int tn = (tid & 15) * 4;      // 0..60
    const int arow = tid >> 1;          // 0..127
    const int ak   = (tid & 1) * 4;     // 0 or 4
    const int brow = tid >> 4;          // 0..7 (tid<128)
    const int bc   = (tid & 15) * 4;    // 0..60

    unsigned long long acc[4][4];       // [m-pair][col]
#pragma unroll
    for (int p = 0; p < 4; p++)
#pragma unroll
        for (int q = 0; q < 4; q++) acc[p][q] = 0ULL;

    for (int k0 = 0; k0 < LAT; k0 += BK) {
        float4 va = *(const float4*)(g_agg + (size_t)(row0 + arow) * LAT + (k0 + ak));
        As[ak + 0][arow] = va.x;
        As[ak + 1][arow] = va.y;
        As[ak + 2][arow] = va.z;
        As[ak + 3][arow] = va.w;
        if (tid < 128) {
            int gc = col0 + bc;
            float4 vb = make_float4(0.f, 0.f, 0.f, 0.f);
            if (gc < HID)
                vb = *(const float4*)(Wf + (size_t)(k0 + brow) * HID + gc);
            // duplicated pairs {x,x,y,y,z,z,w,w}
            *(float4*)&Bsd[brow][2 * bc]     = make_float4(vb.x, vb.x, vb.y, vb.y);
            *(float4*)&Bsd[brow][2 * bc + 4] = make_float4(vb.z, vb.z, vb.w, vb.w);
        }
        __syncthreads();
#pragma unroll
        for (int k = 0; k < BK; k++) {
            ulonglong2 a01 = *(const ulonglong2*)&As[k][tm];       // pairs (m,m+1)(m+2,m+3)
            ulonglong2 a23 = *(const ulonglong2*)&As[k][tm + 4];
            ulonglong2 b01 = *(const ulonglong2*)&Bsd[k][2 * tn];      // dup cols tn, tn+1
            ulonglong2 b23 = *(const ulonglong2*)&Bsd[k][2 * tn + 4];  // dup cols tn+2, tn+3
            acc[0][0] = fma2(a01.x, b01.x, acc[0][0]);
            acc[0][1] = fma2(a01.x, b01.y, acc[0][1]);
            acc[0][2] = fma2(a01.x, b23.x, acc[0][2]);
            acc[0][3] = fma2(a01.x, b23.y, acc[0][3]);
            acc[1][0] = fma2(a01.y, b01.x, acc[1][0]);
            acc[1][1] = fma2(a01.y, b01.y, acc[1][1]);
            acc[1][2] = fma2(a01.y, b23.x, acc[1][2]);
            acc[1][3] = fma2(a01.y, b23.y, acc[1][3]);
            acc[2][0] = fma2(a23.x, b01.x, acc[2][0]);
            acc[2][1] = fma2(a23.x, b01.y, acc[2][1]);
            acc[2][2] = fma2(a23.x, b23.x, acc[2][2]);
            acc[2][3] = fma2(a23.x, b23.y, acc[2][3]);
            acc[3][0] = fma2(a23.y, b01.x, acc[3][0]);
            acc[3][1] = fma2(a23.y, b01.y, acc[3][1]);
            acc[3][2] = fma2(a23.y, b23.x, acc[3][2]);
            acc[3][3] = fma2(a23.y, b23.y, acc[3][3]);
        }
        __syncthreads();
    }
    int gc = col0 + tn;
    if (gc < HID) {   // HID%4==0 so the whole float4 is valid
        float bb[4];
#pragma unroll
        for (int q = 0; q < 4; q++) bb[q] = bf[gc + q];
#pragma unroll
        for (int p = 0; p < 4; p++) {
            float2 u0 = unpack2(acc[p][0]);
            float2 u1 = unpack2(acc[p][1]);
            float2 u2 = unpack2(acc[p][2]);
            float2 u3 = unpack2(acc[p][3]);
            int r = row0 + tm + 2 * p;
            float4 vlo = make_float4(fmaxf(u0.x + bb[0], 0.f), fmaxf(u1.x + bb[1], 0.f),
                                     fmaxf(u2.x + bb[2], 0.f), fmaxf(u3.x + bb[3], 0.f));
            float4 vhi = make_float4(fmaxf(u0.y + bb[0], 0.f), fmaxf(u1.y + bb[1], 0.f),
                                     fmaxf(u2.y + bb[2], 0.f), fmaxf(u3.y + bb[3], 0.f));
            *(float4*)(g_fc1 + (size_t)r * HID + gc)       = vlo;
            *(float4*)(g_fc1 + (size_t)(r + 1) * HID + gc) = vhi;
        }
    }
}

// ---------------- out: [8192,300] @ [300,22] + out_b ----------------------
__global__ __launch_bounds__(256) void k_out(const float* __restrict__ Wo,
                                             const float* __restrict__ bo,
                                             float* __restrict__ out) {
    __shared__ float sW[HID * NC];
    __shared__ float sb[NC];
    for (int t = threadIdx.x; t < HID * NC; t += 256) sW[t] = Wo[t];
    if (threadIdx.x < NC) sb[threadIdx.x] = bo[threadIdx.x];
    __syncthreads();
    int w = threadIdx.x >> 5, lane = threadIdx.x & 31;
    int rbase = blockIdx.x * 64 + w * 8;
#pragma unroll 1
    for (int r8 = 0; r8 < 8; r8++) {
        int r = rbase + r8;
        const float4* fr4 = (const float4*)(g_fc1 + (size_t)r * HID);
        if (lane < NC) {
            float accv = 0.f;
#pragma unroll 5
            for (int k4 = 0; k4 < HID / 4; k4++) {
                float4 v = fr4[k4];
                int k = 4 * k4;
                accv = fmaf(v.x, sW[(k + 0) * NC + lane], accv);
                accv = fmaf(v.y, sW[(k + 1) * NC + lane], accv);
                accv = fmaf(v.z, sW[(k + 2) * NC + lane], accv);
                accv = fmaf(v.w, sW[(k + 3) * NC + lane], accv);
            }
            out[(size_t)r * NC + lane] = accv + sb[lane];
        }
    }
}

// ---------------- launch --------------------------------------------------
extern "C" void kernel_launch(void* const* d_in, const int* in_sizes, int n_in,
                              void* d_out, int out_size) {
    const float* x    = (const float*)d_in[0];
    const void*  ei   = d_in[1];
    const float* W1   = (const float*)d_in[3];
    const float* b1   = (const float*)d_in[4];
    const float* W2   = (const float*)d_in[5];
    const float* b2   = (const float*)d_in[6];
    const float* fc1W = (const float*)d_in[7];
    const float* fc1b = (const float*)d_in[8];
    const float* outW = (const float*)d_in[9];
    const float* outb = (const float*)d_in[10];
    float* out = (float*)d_out;

    int N = in_sizes[0] / SEQL;
    int E = in_sizes[1] / 2;
    int nb = (N + 255) / 256;
    int eb = (E + 255) / 256;
    int gb = (N * 5 + GT - 1) / GT;

    k_detect<<<1, 32>>>((const int*)ei);
    k_deg_init<<<nb, 256>>>(N);
    k_edges_prep<<<eb, 256>>>(ei, E);
    k_offsets<<<nb, 256>>>(N);
    k_place<<<eb, 256>>>(E);

    k_mm20<0><<<nb, 256>>>(x, W1, N);        // x -> g_hs (h1 raw)
    k_gather<<<gb, GT>>>(b1, N);             // g_hs -> g_agg (t1)
    k_mm20<1><<<nb, 256>>>(x, W2, N);        // g_agg -> g_hs (h2 raw)
    k_gather<<<gb, GT>>>(b2, N);             // g_hs -> g_agg (latent)

    dim3 gfc(NBATCH / BM, (HID + BN - 1) / BN);
    k_fc1<<<gfc, 256>>>(fc1W, fc1b);
    k_out<<<NBATCH / 64, 256>>>(outW, outb, out);
}